// round 1
// baseline (speedup 1.0000x reference)
#include <cuda_runtime.h>
#include <math.h>

#define Nn 20000
#define INF 256
#define HID 256
#define ZD 64
#define E2 240000     // directed encoder edges (2E)
#define EP 120000     // positive edges
#define EN 600000     // negative edges
#define ET 720000     // EP+EN

// ---------------- scratch (static __device__, no allocs) ----------------
__device__ float g_m1[Nn * HID];        // x@W1, then reused as h1
__device__ float g_agg1[Nn * HID];      // encoder scatter target
__device__ float g_mlv[Nn * 128];       // [mu_m | lv_m] pre-scatter
__device__ float g_mulv[Nn * 128];      // aggregated mu|lv
__device__ float g_z[Nn * ZD];
__device__ float g_dm[Nn * ZD];         // decoder pre-scatter m
__device__ float g_hA[Nn * ZD];         // decoder pass-1 output
__device__ float g_hB[Nn * ZD];         // decoder pass-2 output
__device__ float g_Pu[Nn * ZD];
__device__ float g_Pv[Nn * ZD];
__device__ float g_dis[Nn];
__device__ int   g_deg[Nn];
__device__ double g_acc[2];             // [0]=recon sum terms, [1]=kl sum terms

// ---------------- zero/init ----------------
__global__ void zero_k() {
    size_t i = (size_t)blockIdx.x * blockDim.x + threadIdx.x;
    size_t stride = (size_t)gridDim.x * blockDim.x;
    for (size_t t = i; t < (size_t)Nn * HID; t += stride) g_agg1[t] = 0.f;
    for (size_t t = i; t < (size_t)Nn * 128; t += stride) g_mulv[t] = 0.f;
    for (size_t t = i; t < (size_t)Nn * ZD; t += stride) { g_hA[t] = 0.f; g_hB[t] = 0.f; }
    for (size_t t = i; t < (size_t)Nn; t += stride) g_deg[t] = 0;
    if (i < 2) g_acc[i] = 0.0;
}

// ---------------- generic tiled fp32 GEMM: C = A@B ----------------
// BM=BN=64, BK=16, 256 threads, 4x4 per thread. N must be mult of 64, K mult of 16.
__global__ void gemm_k(const float* __restrict__ A, const float* __restrict__ B,
                       float* __restrict__ C, int M, int Ncols, int K,
                       int lda, int ldb, int ldc)
{
    __shared__ float As[16][64];
    __shared__ float Bs[16][64];
    int tid = threadIdx.x;
    int tx = tid & 15, ty = tid >> 4;
    int bm0 = blockIdx.y * 64, bn0 = blockIdx.x * 64;

    float acc[4][4] = {};
    for (int k0 = 0; k0 < K; k0 += 16) {
        {
            int r = tid >> 2, kk = (tid & 3) << 2;
            float4 v = make_float4(0.f, 0.f, 0.f, 0.f);
            if (bm0 + r < M)
                v = *(const float4*)(A + (size_t)(bm0 + r) * lda + k0 + kk);
            As[kk + 0][r] = v.x; As[kk + 1][r] = v.y;
            As[kk + 2][r] = v.z; As[kk + 3][r] = v.w;
        }
        {
            int kk = tid >> 4, c = (tid & 15) << 2;
            float4 v = *(const float4*)(B + (size_t)(k0 + kk) * ldb + bn0 + c);
            *(float4*)&Bs[kk][c] = v;
        }
        __syncthreads();
        #pragma unroll
        for (int kk = 0; kk < 16; kk++) {
            float4 a = *(const float4*)&As[kk][ty * 4];
            float4 b = *(const float4*)&Bs[kk][tx * 4];
            float av[4] = {a.x, a.y, a.z, a.w};
            float bv[4] = {b.x, b.y, b.z, b.w};
            #pragma unroll
            for (int i = 0; i < 4; i++)
                #pragma unroll
                for (int j = 0; j < 4; j++)
                    acc[i][j] += av[i] * bv[j];
        }
        __syncthreads();
    }
    #pragma unroll
    for (int i = 0; i < 4; i++) {
        int row = bm0 + ty * 4 + i;
        if (row < M)
            *(float4*)(C + (size_t)row * ldc + bn0 + tx * 4) =
                make_float4(acc[i][0], acc[i][1], acc[i][2], acc[i][3]);
    }
}

// ---------------- unnormalized scatter-add: out[dst] += m[src], width = W4*4 ----------------
__global__ void scatter_add_k(const float* __restrict__ m, float* __restrict__ out,
                              const int* __restrict__ src, const int* __restrict__ dst,
                              int nmsg, int W4)
{
    int idx = blockIdx.x * blockDim.x + threadIdx.x;
    int total = nmsg * W4;
    if (idx >= total) return;
    int e = idx / W4, c = idx - e * W4;
    int s = src[e], d = dst[e];
    float4 v = ((const float4*)m)[(size_t)s * W4 + c];
    float* o = out + ((size_t)d * W4 + c) * 4;
    atomicAdd(o + 0, v.x); atomicAdd(o + 1, v.y);
    atomicAdd(o + 2, v.z); atomicAdd(o + 3, v.w);
}

// ---------------- LayerNorm + ReLU over rows of 256 (warp per row) ----------------
__global__ void ln_relu_k(const float* __restrict__ b1, const float* __restrict__ g1,
                          const float* __restrict__ bt1)
{
    int row = blockIdx.x * (blockDim.x >> 5) + (threadIdx.x >> 5);
    int lane = threadIdx.x & 31;
    if (row >= Nn) return;
    const float* in = g_agg1 + (size_t)row * 256;
    float v[8];
    float s = 0.f;
    #pragma unroll
    for (int i = 0; i < 8; i++) { v[i] = in[i * 32 + lane] + b1[i * 32 + lane]; s += v[i]; }
    #pragma unroll
    for (int o = 16; o; o >>= 1) s += __shfl_xor_sync(0xffffffffu, s, o);
    float mu = s * (1.0f / 256.0f);
    float vs = 0.f;
    #pragma unroll
    for (int i = 0; i < 8; i++) { float d = v[i] - mu; vs += d * d; }
    #pragma unroll
    for (int o = 16; o; o >>= 1) vs += __shfl_xor_sync(0xffffffffu, vs, o);
    float rs = rsqrtf(vs * (1.0f / 256.0f) + 1e-5f);
    float* outp = g_m1 + (size_t)row * 256;
    #pragma unroll
    for (int i = 0; i < 8; i++) {
        int c = i * 32 + lane;
        outp[c] = fmaxf((v[i] - mu) * rs * g1[c] + bt1[c], 0.f);
    }
}

// ---------------- z + KL ----------------
__global__ void z_kl_k(const float* __restrict__ eps, const float* __restrict__ bmu,
                       const float* __restrict__ blv)
{
    __shared__ float red[256];
    int idx = blockIdx.x * 256 + threadIdx.x;   // over Nn*ZD = 1,280,000
    float t = 0.f;
    if (idx < Nn * ZD) {
        int n = idx >> 6, j = idx & 63;
        float mu = g_mulv[(size_t)n * 128 + j] + bmu[j];
        float lv = g_mulv[(size_t)n * 128 + 64 + j] + blv[j];
        g_z[idx] = mu + eps[idx] * expf(0.5f * lv);
        t = 1.0f + lv - mu * mu - expf(lv);
    }
    red[threadIdx.x] = t;
    __syncthreads();
    for (int s = 128; s; s >>= 1) {
        if (threadIdx.x < s) red[threadIdx.x] += red[threadIdx.x + s];
        __syncthreads();
    }
    if (threadIdx.x == 0) atomicAdd(&g_acc[1], (double)red[0]);
}

// ---------------- decoder degree / norm ----------------
__global__ void deg_k(const int* __restrict__ pd) {
    int e = blockIdx.x * blockDim.x + threadIdx.x;
    if (e < EP) atomicAdd(&g_deg[pd[e]], 1);
}
__global__ void dis_k() {
    int n = blockIdx.x * blockDim.x + threadIdx.x;
    if (n < Nn) g_dis[n] = rsqrtf((float)g_deg[n] + 1.0f);
}

// normalized scatter: out[d] += m[s]*dis[s]*dis[d]  (width 64, W4=16)
__global__ void scat_norm_k(const float* __restrict__ m, float* __restrict__ out,
                            const int* __restrict__ ps, const int* __restrict__ pd)
{
    int idx = blockIdx.x * blockDim.x + threadIdx.x;
    if (idx >= EP * 16) return;
    int e = idx >> 4, c = idx & 15;
    int s = ps[e], d = pd[e];
    float nrm = g_dis[s] * g_dis[d];
    float4 v = ((const float4*)m)[(size_t)s * 16 + c];
    float* o = out + ((size_t)d * 16 + c) * 4;
    atomicAdd(o + 0, v.x * nrm); atomicAdd(o + 1, v.y * nrm);
    atomicAdd(o + 2, v.z * nrm); atomicAdd(o + 3, v.w * nrm);
}

// add self loop + bias + relu (in place on the agg buffer)
__global__ void relu_dec_k(const float* __restrict__ m, float* __restrict__ h,
                           const float* __restrict__ bd)
{
    int idx = blockIdx.x * blockDim.x + threadIdx.x;
    if (idx >= Nn * ZD) return;
    int n = idx >> 6, j = idx & 63;
    float dn = g_dis[n];
    h[idx] = fmaxf(h[idx] + m[idx] * dn * dn + bd[j], 0.f);
}

// ---------------- fused edge MLP + weighted BCE ----------------
// logits_e = Wb^T relu( Pu[u] + Pv[v] + ba + A_d|hu-hv| + A_p(hu*hv) ) + bb, /tau
// 2 edges per warp to amortize shared-W traffic.
__global__ void edge_mlp_k(const float* __restrict__ Wa, const float* __restrict__ ba,
                           const float* __restrict__ Wb, const float* __restrict__ bb,
                           const int* __restrict__ ps, const int* __restrict__ pd,
                           const int* __restrict__ nu, const int* __restrict__ nv,
                           const float* __restrict__ tau)
{
    __shared__ float2 sW[64 * 64];       // (A_d, A_p) interleaved, 32 KB
    __shared__ float2 sdp[8][2][64];     // per-warp, per-edge-slot (|d|, prod)

    int tid = threadIdx.x;
    for (int i = tid; i < 4096; i += blockDim.x) {
        int j = i >> 6, o = i & 63;
        sW[i] = make_float2(Wa[(128 + j) * 64 + o], Wa[(192 + j) * 64 + o]);
    }
    __syncthreads();

    int warp = tid >> 5, lane = tid & 31;
    float wb0 = Wb[lane], wb1 = Wb[lane + 32];
    float ba0 = ba[lane], ba1 = ba[lane + 32];
    float inv_tau = 1.0f / fmaxf(*tau, 1e-4f);
    double lsum = 0.0;

    int gw = blockIdx.x * 8 + warp;
    int nwarps = gridDim.x * 8;
    for (int p = gw; p < ET / 2; p += nwarps) {
        float acc[2][2];
        __syncwarp();
        #pragma unroll
        for (int s = 0; s < 2; s++) {
            int e = 2 * p + s;
            int u, v;
            if (e < EP) { u = ps[e]; v = pd[e]; }
            else        { u = nu[e - EP]; v = nv[e - EP]; }
            float a0 = g_hB[(size_t)u * 64 + lane],      a1 = g_hB[(size_t)u * 64 + 32 + lane];
            float b0 = g_hB[(size_t)v * 64 + lane],      b1 = g_hB[(size_t)v * 64 + 32 + lane];
            sdp[warp][s][lane]      = make_float2(fabsf(a0 - b0), a0 * b0);
            sdp[warp][s][lane + 32] = make_float2(fabsf(a1 - b1), a1 * b1);
            acc[s][0] = g_Pu[(size_t)u * 64 + lane]      + g_Pv[(size_t)v * 64 + lane]      + ba0;
            acc[s][1] = g_Pu[(size_t)u * 64 + 32 + lane] + g_Pv[(size_t)v * 64 + 32 + lane] + ba1;
        }
        __syncwarp();
        #pragma unroll 8
        for (int j = 0; j < 64; j++) {
            float2 w0 = sW[j * 64 + lane];
            float2 w1 = sW[j * 64 + 32 + lane];
            float2 d0 = sdp[warp][0][j];
            float2 d1 = sdp[warp][1][j];
            acc[0][0] += d0.x * w0.x + d0.y * w0.y;
            acc[0][1] += d0.x * w1.x + d0.y * w1.y;
            acc[1][0] += d1.x * w0.x + d1.y * w0.y;
            acc[1][1] += d1.x * w1.x + d1.y * w1.y;
        }
        #pragma unroll
        for (int s = 0; s < 2; s++) {
            float r = fmaxf(acc[s][0], 0.f) * wb0 + fmaxf(acc[s][1], 0.f) * wb1;
            #pragma unroll
            for (int o = 16; o; o >>= 1) r += __shfl_xor_sync(0xffffffffu, r, o);
            if (lane == 0) {
                int e = 2 * p + s;
                float logit = (r + bb[0]) * inv_tau;
                float x = (e < EP) ? logit : -logit;
                // log_sigmoid(x), numerically stable
                float ls = fminf(x, 0.f) - log1pf(expf(-fabsf(x)));
                lsum += (e < EP) ? 5.0 * (double)ls : (double)ls;
            }
        }
    }
    if (lane == 0) atomicAdd(&g_acc[0], lsum);
}

// ---------------- finalize ----------------
__global__ void fin_k(float* out) {
    float recon = -(float)(g_acc[0] / (double)ET);
    float kl = -0.5f * (float)(g_acc[1] / (double)(Nn * ZD));
    out[0] = recon + kl;
    out[1] = recon;
    out[2] = kl;
}

// ---------------- launch ----------------
extern "C" void kernel_launch(void* const* d_in, const int* in_sizes, int n_in,
                              void* d_out, int out_size)
{
    const float* x    = (const float*)d_in[0];
    const float* eps  = (const float*)d_in[1];
    const int* eidx   = (const int*)d_in[2];     // [2, 240000]
    const int* pedge  = (const int*)d_in[3];     // [2, 120000]
    const int* nedge  = (const int*)d_in[4];     // [2, 600000]
    const float* W1   = (const float*)d_in[5];
    const float* b1   = (const float*)d_in[6];
    const float* g1   = (const float*)d_in[7];
    const float* bt1  = (const float*)d_in[8];
    const float* Wmu  = (const float*)d_in[9];
    const float* bmu  = (const float*)d_in[10];
    const float* Wlv  = (const float*)d_in[11];
    const float* blv  = (const float*)d_in[12];
    const float* Wd1  = (const float*)d_in[13];
    const float* bd1  = (const float*)d_in[14];
    const float* Wd2  = (const float*)d_in[15];
    const float* bd2  = (const float*)d_in[16];
    const float* Wa   = (const float*)d_in[17];
    const float* ba   = (const float*)d_in[18];
    const float* Wb   = (const float*)d_in[19];
    const float* bb   = (const float*)d_in[20];
    const float* tau  = (const float*)d_in[21];

    const int* src = eidx;
    const int* dst = eidx + E2;
    const int* ps  = pedge;
    const int* pd  = pedge + EP;
    const int* nu  = nedge;
    const int* nv  = nedge + EN;

    // scratch pointers via symbols are baked into kernels; compute via device pointers
    float *p_m1, *p_mlv, *p_mulv, *p_z, *p_dm, *p_hA, *p_hB, *p_Pu, *p_Pv, *p_agg1;
    cudaGetSymbolAddress((void**)&p_m1, g_m1);
    cudaGetSymbolAddress((void**)&p_agg1, g_agg1);
    cudaGetSymbolAddress((void**)&p_mlv, g_mlv);
    cudaGetSymbolAddress((void**)&p_mulv, g_mulv);
    cudaGetSymbolAddress((void**)&p_z, g_z);
    cudaGetSymbolAddress((void**)&p_dm, g_dm);
    cudaGetSymbolAddress((void**)&p_hA, g_hA);
    cudaGetSymbolAddress((void**)&p_hB, g_hB);
    cudaGetSymbolAddress((void**)&p_Pu, g_Pu);
    cudaGetSymbolAddress((void**)&p_Pv, g_Pv);

    zero_k<<<2048, 256>>>();

    // encoder: m1 = x @ W1
    gemm_k<<<dim3(4, 313), 256>>>(x, W1, p_m1, Nn, 256, 256, 256, 256, 256);
    // agg1 = scatter_add(m1[src] -> dst)
    scatter_add_k<<<(E2 * 64 + 255) / 256, 256>>>(p_m1, p_agg1, src, dst, E2, 64);
    // h1 = relu(LN(agg1 + b1)) -> overwrites m1
    ln_relu_k<<<2500, 256>>>(b1, g1, bt1);

    // mu/lv pre-scatter GEMMs into [mu|lv] buffer
    gemm_k<<<dim3(1, 313), 256>>>(p_m1, Wmu, p_mlv,      Nn, 64, 256, 256, 64, 128);
    gemm_k<<<dim3(1, 313), 256>>>(p_m1, Wlv, p_mlv + 64, Nn, 64, 256, 256, 64, 128);
    scatter_add_k<<<(E2 * 32 + 255) / 256, 256>>>(p_mlv, p_mulv, src, dst, E2, 32);

    // z, KL
    z_kl_k<<<5000, 256>>>(eps, bmu, blv);

    // decoder normalization
    deg_k<<<(EP + 255) / 256, 256>>>(pd);
    dis_k<<<(Nn + 255) / 256, 256>>>();

    // decoder pass 1
    gemm_k<<<dim3(1, 313), 256>>>(p_z, Wd1, p_dm, Nn, 64, 64, 64, 64, 64);
    scat_norm_k<<<(EP * 16 + 255) / 256, 256>>>(p_dm, p_hA, ps, pd);
    relu_dec_k<<<(Nn * 64 + 255) / 256, 256>>>(p_dm, p_hA, bd1);

    // decoder pass 2
    gemm_k<<<dim3(1, 313), 256>>>(p_hA, Wd2, p_dm, Nn, 64, 64, 64, 64, 64);
    scat_norm_k<<<(EP * 16 + 255) / 256, 256>>>(p_dm, p_hB, ps, pd);
    relu_dec_k<<<(Nn * 64 + 255) / 256, 256>>>(p_dm, p_hB, bd2);

    // node-factored MLP halves: Pu = h2 @ Wa[0:64], Pv = h2 @ Wa[64:128]
    gemm_k<<<dim3(1, 313), 256>>>(p_hB, Wa,           p_Pu, Nn, 64, 64, 64, 64, 64);
    gemm_k<<<dim3(1, 313), 256>>>(p_hB, Wa + 64 * 64, p_Pv, Nn, 64, 64, 64, 64, 64);

    // fused edge MLP + weighted BCE
    edge_mlp_k<<<3000, 256>>>(Wa, ba, Wb, bb, ps, pd, nu, nv, tau);

    fin_k<<<1, 1>>>((float*)d_out);
}

// round 5
// speedup vs baseline: 1.4418x; 1.4418x over previous
#include <cuda_runtime.h>
#include <math.h>

#define Nn 20000
#define HID 256
#define ZD 64
#define E2 240000     // directed encoder edges (2E)
#define EP 120000     // positive edges
#define EN 600000     // negative edges
#define ET 720000     // EP+EN

typedef unsigned long long ull;

// ---------------- f32x2 packed-math helpers (Blackwell FFMA2) ----------------
__device__ __forceinline__ ull splat2(float v) {
    ull r; asm("mov.b64 %0, {%1, %1};" : "=l"(r) : "f"(v)); return r;
}
__device__ __forceinline__ ull pack2(float lo, float hi) {
    ull r; asm("mov.b64 %0, {%1, %2};" : "=l"(r) : "f"(lo), "f"(hi)); return r;
}
__device__ __forceinline__ ull fma2(ull a, ull b, ull c) {
    ull d; asm("fma.rn.f32x2 %0, %1, %2, %3;" : "=l"(d) : "l"(a), "l"(b), "l"(c)); return d;
}
__device__ __forceinline__ float2 unpack2(ull v) {
    float2 f; asm("mov.b64 {%0, %1}, %2;" : "=f"(f.x), "=f"(f.y) : "l"(v)); return f;
}
// vectorized global reduction (sm_90+)
__device__ __forceinline__ void red_add_v4(float* p, float a, float b, float c, float d) {
    asm volatile("red.global.add.v4.f32 [%0], {%1, %2, %3, %4};"
                 :: "l"(p), "f"(a), "f"(b), "f"(c), "f"(d) : "memory");
}

// ---------------- scratch (static __device__, no allocs) ----------------
__device__ float g_m1[Nn * HID];        // x@W1, then reused as h1
__device__ float g_agg1[Nn * HID];      // encoder scatter target
__device__ float g_mlv[Nn * 128];       // [mu_m | lv_m] pre-scatter
__device__ float g_mulv[Nn * 128];      // aggregated mu|lv
__device__ float g_z[Nn * ZD];
__device__ float g_dm[Nn * ZD];         // decoder pre-scatter m
__device__ float g_hA[Nn * ZD];         // decoder pass-1 output
__device__ float g_hB[Nn * ZD];         // decoder pass-2 output
__device__ float g_Pu[Nn * ZD];
__device__ float g_Pv[Nn * ZD];
__device__ float g_dis[Nn];
__device__ int   g_deg[Nn];
__device__ double g_acc[2];             // [0]=recon sum, [1]=kl sum

// ---------------- zero/init ----------------
__global__ void zero_k() {
    size_t i = (size_t)blockIdx.x * blockDim.x + threadIdx.x;
    size_t stride = (size_t)gridDim.x * blockDim.x;
    for (size_t t = i; t < (size_t)Nn * HID; t += stride) g_agg1[t] = 0.f;
    for (size_t t = i; t < (size_t)Nn * 128; t += stride) g_mulv[t] = 0.f;
    for (size_t t = i; t < (size_t)Nn * ZD; t += stride) { g_hA[t] = 0.f; g_hB[t] = 0.f; }
    for (size_t t = i; t < (size_t)Nn; t += stride) g_deg[t] = 0;
    if (i < 2) g_acc[i] = 0.0;
}

// ---------------- tiled fp32 GEMM with FFMA2: C = A@B ----------------
// BM=BN=64, BK=16, 256 threads, 4x4 per thread (packed as 4x(2x2)).
__global__ void gemm_k(const float* __restrict__ A, const float* __restrict__ B,
                       float* __restrict__ C, int M, int Ncols, int K,
                       int lda, int ldb, int ldc)
{
    __shared__ float As[16][64];
    __shared__ float Bs[16][64];
    int tid = threadIdx.x;
    int tx = tid & 15, ty = tid >> 4;
    int bm0 = blockIdx.y * 64, bn0 = blockIdx.x * 64;

    ull pacc[4][2];
    #pragma unroll
    for (int i = 0; i < 4; i++) { pacc[i][0] = 0ull; pacc[i][1] = 0ull; }

    for (int k0 = 0; k0 < K; k0 += 16) {
        {
            int r = tid >> 2, kk = (tid & 3) << 2;
            float4 v = make_float4(0.f, 0.f, 0.f, 0.f);
            if (bm0 + r < M)
                v = *(const float4*)(A + (size_t)(bm0 + r) * lda + k0 + kk);
            As[kk + 0][r] = v.x; As[kk + 1][r] = v.y;
            As[kk + 2][r] = v.z; As[kk + 3][r] = v.w;
        }
        {
            int kk = tid >> 4, c = (tid & 15) << 2;
            float4 v = *(const float4*)(B + (size_t)(k0 + kk) * ldb + bn0 + c);
            *(float4*)&Bs[kk][c] = v;
        }
        __syncthreads();
        #pragma unroll
        for (int kk = 0; kk < 16; kk++) {
            float4 a = *(const float4*)&As[kk][ty * 4];
            const ull* bp = (const ull*)&Bs[kk][tx * 4];
            ull b01 = bp[0], b23 = bp[1];
            float av[4] = {a.x, a.y, a.z, a.w};
            #pragma unroll
            for (int i = 0; i < 4; i++) {
                ull as = splat2(av[i]);
                pacc[i][0] = fma2(b01, as, pacc[i][0]);
                pacc[i][1] = fma2(b23, as, pacc[i][1]);
            }
        }
        __syncthreads();
    }
    #pragma unroll
    for (int i = 0; i < 4; i++) {
        int row = bm0 + ty * 4 + i;
        if (row < M) {
            float2 lo = unpack2(pacc[i][0]);
            float2 hi = unpack2(pacc[i][1]);
            *(float4*)(C + (size_t)row * ldc + bn0 + tx * 4) =
                make_float4(lo.x, lo.y, hi.x, hi.y);
        }
    }
}

// ---------------- unnormalized scatter-add: out[dst] += m[src], width = W4*4 ----------------
__global__ void scatter_add_k(const float* __restrict__ m, float* __restrict__ out,
                              const int* __restrict__ src, const int* __restrict__ dst,
                              int nmsg, int W4)
{
    int idx = blockIdx.x * blockDim.x + threadIdx.x;
    int total = nmsg * W4;
    if (idx >= total) return;
    int e = idx / W4, c = idx - e * W4;
    int s = src[e], d = dst[e];
    float4 v = ((const float4*)m)[(size_t)s * W4 + c];
    float* o = out + ((size_t)d * W4 + c) * 4;
    red_add_v4(o, v.x, v.y, v.z, v.w);
}

// ---------------- LayerNorm + ReLU over rows of 256 (warp per row) ----------------
__global__ void ln_relu_k(const float* __restrict__ b1, const float* __restrict__ g1,
                          const float* __restrict__ bt1)
{
    int row = blockIdx.x * (blockDim.x >> 5) + (threadIdx.x >> 5);
    int lane = threadIdx.x & 31;
    if (row >= Nn) return;
    const float* in = g_agg1 + (size_t)row * 256;
    float v[8];
    float s = 0.f;
    #pragma unroll
    for (int i = 0; i < 8; i++) { v[i] = in[i * 32 + lane] + b1[i * 32 + lane]; s += v[i]; }
    #pragma unroll
    for (int o = 16; o; o >>= 1) s += __shfl_xor_sync(0xffffffffu, s, o);
    float mu = s * (1.0f / 256.0f);
    float vs = 0.f;
    #pragma unroll
    for (int i = 0; i < 8; i++) { float d = v[i] - mu; vs += d * d; }
    #pragma unroll
    for (int o = 16; o; o >>= 1) vs += __shfl_xor_sync(0xffffffffu, vs, o);
    float rs = rsqrtf(vs * (1.0f / 256.0f) + 1e-5f);
    float* outp = g_m1 + (size_t)row * 256;
    #pragma unroll
    for (int i = 0; i < 8; i++) {
        int c = i * 32 + lane;
        outp[c] = fmaxf((v[i] - mu) * rs * g1[c] + bt1[c], 0.f);
    }
}

// ---------------- z + KL ----------------
__global__ void z_kl_k(const float* __restrict__ eps, const float* __restrict__ bmu,
                       const float* __restrict__ blv)
{
    __shared__ float red[256];
    int idx = blockIdx.x * 256 + threadIdx.x;   // over Nn*ZD
    float t = 0.f;
    if (idx < Nn * ZD) {
        int n = idx >> 6, j = idx & 63;
        float mu = g_mulv[(size_t)n * 128 + j] + bmu[j];
        float lv = g_mulv[(size_t)n * 128 + 64 + j] + blv[j];
        g_z[idx] = mu + eps[idx] * expf(0.5f * lv);
        t = 1.0f + lv - mu * mu - expf(lv);
    }
    red[threadIdx.x] = t;
    __syncthreads();
    for (int s = 128; s; s >>= 1) {
        if (threadIdx.x < s) red[threadIdx.x] += red[threadIdx.x + s];
        __syncthreads();
    }
    if (threadIdx.x == 0) atomicAdd(&g_acc[1], (double)red[0]);
}

// ---------------- decoder degree / norm ----------------
__global__ void deg_k(const int* __restrict__ pd) {
    int e = blockIdx.x * blockDim.x + threadIdx.x;
    if (e < EP) atomicAdd(&g_deg[pd[e]], 1);
}
__global__ void dis_k() {
    int n = blockIdx.x * blockDim.x + threadIdx.x;
    if (n < Nn) g_dis[n] = rsqrtf((float)g_deg[n] + 1.0f);
}

// normalized scatter: out[d] += m[s]*dis[s]*dis[d]  (width 64, W4=16)
__global__ void scat_norm_k(const float* __restrict__ m, float* __restrict__ out,
                            const int* __restrict__ ps, const int* __restrict__ pd)
{
    int idx = blockIdx.x * blockDim.x + threadIdx.x;
    if (idx >= EP * 16) return;
    int e = idx >> 4, c = idx & 15;
    int s = ps[e], d = pd[e];
    float nrm = g_dis[s] * g_dis[d];
    float4 v = ((const float4*)m)[(size_t)s * 16 + c];
    float* o = out + ((size_t)d * 16 + c) * 4;
    red_add_v4(o, v.x * nrm, v.y * nrm, v.z * nrm, v.w * nrm);
}

// add self loop + bias + relu (in place on the agg buffer)
__global__ void relu_dec_k(const float* __restrict__ m, float* __restrict__ h,
                           const float* __restrict__ bd)
{
    int idx = blockIdx.x * blockDim.x + threadIdx.x;
    if (idx >= Nn * ZD) return;
    int n = idx >> 6, j = idx & 63;
    float dn = g_dis[n];
    h[idx] = fmaxf(h[idx] + m[idx] * dn * dn + bd[j], 0.f);
}

// ---------------- fused edge MLP + weighted BCE (FFMA2, 8 edges/warp) ----------------
// logits_e = Wb^T relu( Pu[u] + Pv[v] + ba + A_d|hu-hv| + A_p(hu*hv) ) + bb, /tau
// Accumulators packed over edge pairs (f32x2). Shared:
//   sW4[j*32+c] = (Ad[j][c], Ap[j][c], Ad[j][c+32], Ap[j][c+32])   32 KB
//   stg[warp][pair][j] = (d_even, d_odd, p_even, p_odd)            32 KB
__global__ void __launch_bounds__(256)
edge_mlp_k(const float* __restrict__ Wa, const float* __restrict__ ba,
           const float* __restrict__ Wb, const float* __restrict__ bb,
           const int* __restrict__ ps, const int* __restrict__ pd,
           const int* __restrict__ nu, const int* __restrict__ nv,
           const float* __restrict__ tau)
{
    extern __shared__ char smemraw[];
    float4* sW4 = (float4*)smemraw;                      // 64*32 float4
    float4* stg = (float4*)(smemraw + 64 * 32 * 16);     // [8][4][64] float4

    int tid = threadIdx.x;
    for (int i = tid; i < 64 * 32; i += blockDim.x) {
        int j = i >> 5, c = i & 31;
        sW4[i] = make_float4(Wa[(128 + j) * 64 + c],      Wa[(192 + j) * 64 + c],
                             Wa[(128 + j) * 64 + 32 + c], Wa[(192 + j) * 64 + 32 + c]);
    }
    __syncthreads();

    int warp = tid >> 5, lane = tid & 31;
    float wb0 = Wb[lane], wb1 = Wb[lane + 32];
    float ba0 = ba[lane], ba1 = ba[lane + 32];
    float inv_tau = 1.0f / fmaxf(tau[0], 1e-4f);
    double lsum = 0.0;
    float4* mystg = stg + warp * 256;

    int gw = blockIdx.x * 8 + warp;
    int nw = gridDim.x * 8;
    const int NT = ET / 8;                               // 90000 tiles of 8 edges
    for (int t = gw; t < NT; t += nw) {
        int e0 = t * 8;
        float ini_lo[8], ini_hi[8];
        __syncwarp();
        #pragma unroll
        for (int s = 0; s < 8; s++) {
            int e = e0 + s;
            int u, v;
            if (e < EP) { u = ps[e]; v = pd[e]; }
            else        { u = nu[e - EP]; v = nv[e - EP]; }
            float al = g_hB[(size_t)u * 64 + lane],      ah = g_hB[(size_t)u * 64 + 32 + lane];
            float bl = g_hB[(size_t)v * 64 + lane],      bh = g_hB[(size_t)v * 64 + 32 + lane];
            int q = s >> 1, o = s & 1;
            float* st  = (float*)&mystg[q * 64 + lane];
            float* st2 = (float*)&mystg[q * 64 + lane + 32];
            st[o]      = fabsf(al - bl);  st[2 + o]  = al * bl;
            st2[o]     = fabsf(ah - bh);  st2[2 + o] = ah * bh;
            ini_lo[s] = g_Pu[(size_t)u * 64 + lane]      + g_Pv[(size_t)v * 64 + lane]      + ba0;
            ini_hi[s] = g_Pu[(size_t)u * 64 + 32 + lane] + g_Pv[(size_t)v * 64 + 32 + lane] + ba1;
        }
        ull accL[4], accH[4];
        #pragma unroll
        for (int q = 0; q < 4; q++) {
            accL[q] = pack2(ini_lo[2 * q], ini_lo[2 * q + 1]);
            accH[q] = pack2(ini_hi[2 * q], ini_hi[2 * q + 1]);
        }
        __syncwarp();
        #pragma unroll 4
        for (int j = 0; j < 64; j++) {
            float4 w = sW4[j * 32 + lane];
            ull wdl = splat2(w.x), wpl = splat2(w.y);
            ull wdh = splat2(w.z), wph = splat2(w.w);
            #pragma unroll
            for (int q = 0; q < 4; q++) {
                const ull* pr = (const ull*)&mystg[q * 64 + j];
                ull dd = pr[0], pp = pr[1];
                accL[q] = fma2(dd, wdl, accL[q]);
                accL[q] = fma2(pp, wpl, accL[q]);
                accH[q] = fma2(dd, wdh, accH[q]);
                accH[q] = fma2(pp, wph, accH[q]);
            }
        }
        #pragma unroll
        for (int s = 0; s < 8; s++) {
            float2 lo = unpack2(accL[s >> 1]);
            float2 hi = unpack2(accH[s >> 1]);
            float vlo = (s & 1) ? lo.y : lo.x;
            float vhi = (s & 1) ? hi.y : hi.x;
            float r = fmaxf(vlo, 0.f) * wb0 + fmaxf(vhi, 0.f) * wb1;
            #pragma unroll
            for (int o = 16; o; o >>= 1) r += __shfl_xor_sync(0xffffffffu, r, o);
            if (lane == 0) {
                int e = e0 + s;
                float logit = (r + bb[0]) * inv_tau;
                float x = (e < EP) ? logit : -logit;
                float ls = fminf(x, 0.f) - log1pf(expf(-fabsf(x)));
                lsum += (e < EP) ? 5.0 * (double)ls : (double)ls;
            }
        }
    }
    if (lane == 0) atomicAdd(&g_acc[0], lsum);
}

// ---------------- finalize ----------------
__global__ void fin_k(float* out) {
    float recon = -(float)(g_acc[0] / (double)ET);
    float kl = -0.5f * (float)(g_acc[1] / (double)(Nn * ZD));
    out[0] = recon + kl;
    out[1] = recon;
    out[2] = kl;
}

// ---------------- launch ----------------
extern "C" void kernel_launch(void* const* d_in, const int* in_sizes, int n_in,
                              void* d_out, int out_size)
{
    const float* x    = (const float*)d_in[0];
    const float* eps  = (const float*)d_in[1];
    const int* eidx   = (const int*)d_in[2];     // [2, 240000]
    const int* pedge  = (const int*)d_in[3];     // [2, 120000]
    const int* nedge  = (const int*)d_in[4];     // [2, 600000]
    const float* W1   = (const float*)d_in[5];
    const float* b1   = (const float*)d_in[6];
    const float* g1   = (const float*)d_in[7];
    const float* bt1  = (const float*)d_in[8];
    const float* Wmu  = (const float*)d_in[9];
    const float* bmu  = (const float*)d_in[10];
    const float* Wlv  = (const float*)d_in[11];
    const float* blv  = (const float*)d_in[12];
    const float* Wd1  = (const float*)d_in[13];
    const float* bd1  = (const float*)d_in[14];
    const float* Wd2  = (const float*)d_in[15];
    const float* bd2  = (const float*)d_in[16];
    const float* Wa   = (const float*)d_in[17];
    const float* ba   = (const float*)d_in[18];
    const float* Wb   = (const float*)d_in[19];
    const float* bb   = (const float*)d_in[20];
    const float* tau  = (const float*)d_in[21];

    const int* src = eidx;
    const int* dst = eidx + E2;
    const int* ps  = pedge;
    const int* pd  = pedge + EP;
    const int* nu  = nedge;
    const int* nv  = nedge + EN;

    float *p_m1, *p_mlv, *p_mulv, *p_z, *p_dm, *p_hA, *p_hB, *p_Pu, *p_Pv, *p_agg1;
    cudaGetSymbolAddress((void**)&p_m1, g_m1);
    cudaGetSymbolAddress((void**)&p_agg1, g_agg1);
    cudaGetSymbolAddress((void**)&p_mlv, g_mlv);
    cudaGetSymbolAddress((void**)&p_mulv, g_mulv);
    cudaGetSymbolAddress((void**)&p_z, g_z);
    cudaGetSymbolAddress((void**)&p_dm, g_dm);
    cudaGetSymbolAddress((void**)&p_hA, g_hA);
    cudaGetSymbolAddress((void**)&p_hB, g_hB);
    cudaGetSymbolAddress((void**)&p_Pu, g_Pu);
    cudaGetSymbolAddress((void**)&p_Pv, g_Pv);

    cudaFuncSetAttribute(edge_mlp_k, cudaFuncAttributeMaxDynamicSharedMemorySize, 65536);

    zero_k<<<2048, 256>>>();

    // encoder: m1 = x @ W1
    gemm_k<<<dim3(4, 313), 256>>>(x, W1, p_m1, Nn, 256, 256, 256, 256, 256);
    // agg1 = scatter_add(m1[src] -> dst)
    scatter_add_k<<<(E2 * 64 + 255) / 256, 256>>>(p_m1, p_agg1, src, dst, E2, 64);
    // h1 = relu(LN(agg1 + b1)) -> overwrites m1
    ln_relu_k<<<2500, 256>>>(b1, g1, bt1);

    // mu/lv pre-scatter GEMMs into [mu|lv] buffer
    gemm_k<<<dim3(1, 313), 256>>>(p_m1, Wmu, p_mlv,      Nn, 64, 256, 256, 64, 128);
    gemm_k<<<dim3(1, 313), 256>>>(p_m1, Wlv, p_mlv + 64, Nn, 64, 256, 256, 64, 128);
    scatter_add_k<<<(E2 * 32 + 255) / 256, 256>>>(p_mlv, p_mulv, src, dst, E2, 32);

    // z, KL
    z_kl_k<<<5000, 256>>>(eps, bmu, blv);

    // decoder normalization
    deg_k<<<(EP + 255) / 256, 256>>>(pd);
    dis_k<<<(Nn + 255) / 256, 256>>>();

    // decoder pass 1
    gemm_k<<<dim3(1, 313), 256>>>(p_z, Wd1, p_dm, Nn, 64, 64, 64, 64, 64);
    scat_norm_k<<<(EP * 16 + 255) / 256, 256>>>(p_dm, p_hA, ps, pd);
    relu_dec_k<<<(Nn * 64 + 255) / 256, 256>>>(p_dm, p_hA, bd1);

    // decoder pass 2
    gemm_k<<<dim3(1, 313), 256>>>(p_hA, Wd2, p_dm, Nn, 64, 64, 64, 64, 64);
    scat_norm_k<<<(EP * 16 + 255) / 256, 256>>>(p_dm, p_hB, ps, pd);
    relu_dec_k<<<(Nn * 64 + 255) / 256, 256>>>(p_dm, p_hB, bd2);

    // node-factored MLP halves: Pu = h2 @ Wa[0:64], Pv = h2 @ Wa[64:128]
    gemm_k<<<dim3(1, 313), 256>>>(p_hB, Wa,           p_Pu, Nn, 64, 64, 64, 64, 64);
    gemm_k<<<dim3(1, 313), 256>>>(p_hB, Wa + 64 * 64, p_Pv, Nn, 64, 64, 64, 64, 64);

    // fused edge MLP + weighted BCE
    edge_mlp_k<<<1184, 256, 65536>>>(Wa, ba, Wb, bb, ps, pd, nu, nv, tau);

    fin_k<<<1, 1>>>((float*)d_out);
}

// round 8
// speedup vs baseline: 1.6472x; 1.1425x over previous
#include <cuda_runtime.h>
#include <cuda_bf16.h>
#include <math.h>

#define Nn 20000
#define HID 256
#define ZD 64
#define E2 240000     // directed encoder edges (2E)
#define EP 120000     // positive edges
#define EN 600000     // negative edges
#define ET 720000     // EP+EN
#define NT64 (ET / 64)     // 11250 tiles of 64 edges

typedef unsigned long long ull;
typedef unsigned int uint32;

// ---------------- f32x2 packed-math helpers ----------------
__device__ __forceinline__ ull splat2(float v) {
    ull r; asm("mov.b64 %0, {%1, %1};" : "=l"(r) : "f"(v)); return r;
}
__device__ __forceinline__ ull fma2(ull a, ull b, ull c) {
    ull d; asm("fma.rn.f32x2 %0, %1, %2, %3;" : "=l"(d) : "l"(a), "l"(b), "l"(c)); return d;
}
__device__ __forceinline__ float2 unpack2(ull v) {
    float2 f; asm("mov.b64 {%0, %1}, %2;" : "=f"(f.x), "=f"(f.y) : "l"(v)); return f;
}
__device__ __forceinline__ void red_add_v4(float* p, float a, float b, float c, float d) {
    asm volatile("red.global.add.v4.f32 [%0], {%1, %2, %3, %4};"
                 :: "l"(p), "f"(a), "f"(b), "f"(c), "f"(d) : "memory");
}
// pack two fp32 -> bf16x2 (lo in low half)
__device__ __forceinline__ uint32 bfp2(float lo, float hi) {
    uint32 r; asm("cvt.rn.bf16x2.f32 %0, %1, %2;" : "=r"(r) : "f"(hi), "f"(lo)); return r;
}
__device__ __forceinline__ uint32 smem_u32(const void* p) {
    uint32 a; asm("{ .reg .u64 t; cvta.to.shared.u64 t, %1; cvt.u32.u64 %0, t; }" : "=r"(a) : "l"(p));
    return a;
}
__device__ __forceinline__ void ldsm4(uint32* r, uint32 addr) {
    asm volatile("ldmatrix.sync.aligned.m8n8.x4.shared.b16 {%0,%1,%2,%3}, [%4];"
        : "=r"(r[0]), "=r"(r[1]), "=r"(r[2]), "=r"(r[3]) : "r"(addr));
}
__device__ __forceinline__ void mma16816(float* c, const uint32* a, uint32 b0, uint32 b1) {
    asm volatile("mma.sync.aligned.m16n8k16.row.col.f32.bf16.bf16.f32 "
        "{%0,%1,%2,%3}, {%4,%5,%6,%7}, {%8,%9}, {%0,%1,%2,%3};"
        : "+f"(c[0]), "+f"(c[1]), "+f"(c[2]), "+f"(c[3])
        : "r"(a[0]), "r"(a[1]), "r"(a[2]), "r"(a[3]), "r"(b0), "r"(b1));
}

// ---------------- scratch ----------------
__device__ float g_m1[Nn * HID];
__device__ float g_agg1[Nn * HID];
__device__ float g_mlv[Nn * 128];
__device__ float g_mulv[Nn * 128];
__device__ float g_z[Nn * ZD];
__device__ float g_dm[Nn * ZD];
__device__ float g_hA[Nn * ZD];
__device__ float g_hB[Nn * ZD];
__device__ float g_dis[Nn];
__device__ int   g_deg[Nn];
__device__ double g_acc[2];

// ---------------- zero/init ----------------
__global__ void zero_k() {
    size_t i = (size_t)blockIdx.x * blockDim.x + threadIdx.x;
    size_t stride = (size_t)gridDim.x * blockDim.x;
    for (size_t t = i; t < (size_t)Nn * HID; t += stride) g_agg1[t] = 0.f;
    for (size_t t = i; t < (size_t)Nn * 128; t += stride) g_mulv[t] = 0.f;
    for (size_t t = i; t < (size_t)Nn * ZD; t += stride) { g_hA[t] = 0.f; g_hB[t] = 0.f; }
    for (size_t t = i; t < (size_t)Nn; t += stride) g_deg[t] = 0;
    if (i < 2) g_acc[i] = 0.0;
}

// ---------------- tiled fp32 GEMM with FFMA2 ----------------
__global__ void gemm_k(const float* __restrict__ A, const float* __restrict__ B,
                       float* __restrict__ C, int M, int Ncols, int K,
                       int lda, int ldb, int ldc)
{
    __shared__ float As[16][64];
    __shared__ float Bs[16][64];
    int tid = threadIdx.x;
    int tx = tid & 15, ty = tid >> 4;
    int bm0 = blockIdx.y * 64, bn0 = blockIdx.x * 64;

    ull pacc[4][2];
    #pragma unroll
    for (int i = 0; i < 4; i++) { pacc[i][0] = 0ull; pacc[i][1] = 0ull; }

    for (int k0 = 0; k0 < K; k0 += 16) {
        {
            int r = tid >> 2, kk = (tid & 3) << 2;
            float4 v = make_float4(0.f, 0.f, 0.f, 0.f);
            if (bm0 + r < M)
                v = *(const float4*)(A + (size_t)(bm0 + r) * lda + k0 + kk);
            As[kk + 0][r] = v.x; As[kk + 1][r] = v.y;
            As[kk + 2][r] = v.z; As[kk + 3][r] = v.w;
        }
        {
            int kk = tid >> 4, c = (tid & 15) << 2;
            float4 v = *(const float4*)(B + (size_t)(k0 + kk) * ldb + bn0 + c);
            *(float4*)&Bs[kk][c] = v;
        }
        __syncthreads();
        #pragma unroll
        for (int kk = 0; kk < 16; kk++) {
            float4 a = *(const float4*)&As[kk][ty * 4];
            const ull* bp = (const ull*)&Bs[kk][tx * 4];
            ull b01 = bp[0], b23 = bp[1];
            float av[4] = {a.x, a.y, a.z, a.w};
            #pragma unroll
            for (int i = 0; i < 4; i++) {
                ull as = splat2(av[i]);
                pacc[i][0] = fma2(b01, as, pacc[i][0]);
                pacc[i][1] = fma2(b23, as, pacc[i][1]);
            }
        }
        __syncthreads();
    }
    #pragma unroll
    for (int i = 0; i < 4; i++) {
        int row = bm0 + ty * 4 + i;
        if (row < M) {
            float2 lo = unpack2(pacc[i][0]);
            float2 hi = unpack2(pacc[i][1]);
            *(float4*)(C + (size_t)row * ldc + bn0 + tx * 4) =
                make_float4(lo.x, lo.y, hi.x, hi.y);
        }
    }
}

// ---------------- scatter-add (REDG.128) ----------------
__global__ void scatter_add_k(const float* __restrict__ m, float* __restrict__ out,
                              const int* __restrict__ src, const int* __restrict__ dst,
                              int nmsg, int W4)
{
    int idx = blockIdx.x * blockDim.x + threadIdx.x;
    int total = nmsg * W4;
    if (idx >= total) return;
    int e = idx / W4, c = idx - e * W4;
    int s = src[e], d = dst[e];
    float4 v = ((const float4*)m)[(size_t)s * W4 + c];
    float* o = out + ((size_t)d * W4 + c) * 4;
    red_add_v4(o, v.x, v.y, v.z, v.w);
}

// ---------------- LayerNorm + ReLU ----------------
__global__ void ln_relu_k(const float* __restrict__ b1, const float* __restrict__ g1,
                          const float* __restrict__ bt1)
{
    int row = blockIdx.x * (blockDim.x >> 5) + (threadIdx.x >> 5);
    int lane = threadIdx.x & 31;
    if (row >= Nn) return;
    const float* in = g_agg1 + (size_t)row * 256;
    float v[8];
    float s = 0.f;
    #pragma unroll
    for (int i = 0; i < 8; i++) { v[i] = in[i * 32 + lane] + b1[i * 32 + lane]; s += v[i]; }
    #pragma unroll
    for (int o = 16; o; o >>= 1) s += __shfl_xor_sync(0xffffffffu, s, o);
    float mu = s * (1.0f / 256.0f);
    float vs = 0.f;
    #pragma unroll
    for (int i = 0; i < 8; i++) { float d = v[i] - mu; vs += d * d; }
    #pragma unroll
    for (int o = 16; o; o >>= 1) vs += __shfl_xor_sync(0xffffffffu, vs, o);
    float rs = rsqrtf(vs * (1.0f / 256.0f) + 1e-5f);
    float* outp = g_m1 + (size_t)row * 256;
    #pragma unroll
    for (int i = 0; i < 8; i++) {
        int c = i * 32 + lane;
        outp[c] = fmaxf((v[i] - mu) * rs * g1[c] + bt1[c], 0.f);
    }
}

// ---------------- z + KL ----------------
__global__ void z_kl_k(const float* __restrict__ eps, const float* __restrict__ bmu,
                       const float* __restrict__ blv)
{
    __shared__ float red[256];
    int idx = blockIdx.x * 256 + threadIdx.x;
    float t = 0.f;
    if (idx < Nn * ZD) {
        int n = idx >> 6, j = idx & 63;
        float mu = g_mulv[(size_t)n * 128 + j] + bmu[j];
        float lv = g_mulv[(size_t)n * 128 + 64 + j] + blv[j];
        g_z[idx] = mu + eps[idx] * expf(0.5f * lv);
        t = 1.0f + lv - mu * mu - expf(lv);
    }
    red[threadIdx.x] = t;
    __syncthreads();
    for (int s = 128; s; s >>= 1) {
        if (threadIdx.x < s) red[threadIdx.x] += red[threadIdx.x + s];
        __syncthreads();
    }
    if (threadIdx.x == 0) atomicAdd(&g_acc[1], (double)red[0]);
}

// ---------------- decoder degree / norm ----------------
__global__ void deg_k(const int* __restrict__ pd) {
    int e = blockIdx.x * blockDim.x + threadIdx.x;
    if (e < EP) atomicAdd(&g_deg[pd[e]], 1);
}
__global__ void dis_k() {
    int n = blockIdx.x * blockDim.x + threadIdx.x;
    if (n < Nn) g_dis[n] = rsqrtf((float)g_deg[n] + 1.0f);
}

__global__ void scat_norm_k(const float* __restrict__ m, float* __restrict__ out,
                            const int* __restrict__ ps, const int* __restrict__ pd)
{
    int idx = blockIdx.x * blockDim.x + threadIdx.x;
    if (idx >= EP * 16) return;
    int e = idx >> 4, c = idx & 15;
    int s = ps[e], d = pd[e];
    float nrm = g_dis[s] * g_dis[d];
    float4 v = ((const float4*)m)[(size_t)s * 16 + c];
    float* o = out + ((size_t)d * 16 + c) * 4;
    red_add_v4(o, v.x * nrm, v.y * nrm, v.z * nrm, v.w * nrm);
}

__global__ void relu_dec_k(const float* __restrict__ m, float* __restrict__ h,
                           const float* __restrict__ bd)
{
    int idx = blockIdx.x * blockDim.x + threadIdx.x;
    if (idx >= Nn * ZD) return;
    int n = idx >> 6, j = idx & 63;
    float dn = g_dis[n];
    h[idx] = fmaxf(h[idx] + m[idx] * dn * dn + bd[j], 0.f);
}

// ---------------- edge MLP via warp-level bf16 mma.sync (HMMA) ----------------
// Tile = 64 edges/block (128 threads, 4 warps, 16 edges/warp).
// A[64 rows][256 cols] bf16 = [hu | hv | |hu-hv| | hu*hv], row stride 264 halfs (528B).
// B = Wt[n][k] = Wa[k*64+n] bf16, 64 rows x 256 cols, stride 528B.
// D = A@Wa: per warp m16n8k16 x (16 k-steps x 8 n-tiles). Epilogue: relu(D+ba)·Wb.
#define ASTR 528
#define EB_OFF 0
#define EA_OFF (64 * ASTR)              // 33792
#define E_SMEM (EA_OFF + 64 * ASTR)     // 67584

__global__ void __launch_bounds__(128)
edge_hmma_k(const float* __restrict__ Wa, const float* __restrict__ ba,
            const float* __restrict__ Wb, const float* __restrict__ bb,
            const int* __restrict__ ps, const int* __restrict__ pd,
            const int* __restrict__ nu, const int* __restrict__ nv,
            const float* __restrict__ tau)
{
    extern __shared__ __align__(16) char smem[];
    uint32 sbase = smem_u32(smem);
    int tid = threadIdx.x;
    int warp = tid >> 5, lane = tid & 31;

    // stage B = Wt[n][k] (one-time)
    for (int idx = tid; idx < 64 * 256; idx += 128) {
        int n = idx & 63, k = idx >> 6;
        *(__nv_bfloat16*)(smem + EB_OFF + n * ASTR + k * 2) =
            __float2bfloat16(Wa[k * 64 + n]);
    }

    // per-thread (Wb, ba) for epilogue columns: col = nt*8 + (lane&3)*2 + j
    float wbv[16], bav[16];
    #pragma unroll
    for (int nt = 0; nt < 8; nt++) {
        #pragma unroll
        for (int j = 0; j < 2; j++) {
            int col = nt * 8 + (lane & 3) * 2 + j;
            wbv[nt * 2 + j] = Wb[col];
            bav[nt * 2 + j] = ba[col];
        }
    }
    float inv_tau = 1.0f / fmaxf(tau[0], 1e-4f);
    float bb0 = bb[0];
    double lsum = 0.0;
    __syncthreads();

    int R = warp * 16;   // warp's edge rows within tile
    // ldmatrix addresses (fixed per lane)
    uint32 a_addr = sbase + EA_OFF + (uint32)(R + (lane & 15)) * ASTR + ((lane >> 4) & 1) * 16;
    uint32 b_base = sbase + EB_OFF + (uint32)(((lane >> 4) & 1) * 8 + (lane & 7)) * ASTR
                    + ((lane >> 3) & 1) * 16;

    for (int t = blockIdx.x; t < NT64; t += gridDim.x) {
        // ---- stage A: thread handles edge r = tid>>1, feature half h = tid&1
        {
            int r = tid >> 1, h = tid & 1;
            int e = t * 64 + r;
            int u, v;
            if (e < EP) { u = ps[e]; v = pd[e]; }
            else        { u = nu[e - EP]; v = nv[e - EP]; }
            const float4* pu = (const float4*)&g_hB[(size_t)u * 64 + h * 32];
            const float4* pv = (const float4*)&g_hB[(size_t)v * 64 + h * 32];
            char* arow = smem + EA_OFF + r * ASTR + h * 64;
            #pragma unroll
            for (int i = 0; i < 8; i++) {
                float4 a = pu[i], b = pv[i];
                uint32 hu0 = bfp2(a.x, a.y), hu1 = bfp2(a.z, a.w);
                uint32 hv0 = bfp2(b.x, b.y), hv1 = bfp2(b.z, b.w);
                uint32 dd0 = bfp2(fabsf(a.x - b.x), fabsf(a.y - b.y));
                uint32 dd1 = bfp2(fabsf(a.z - b.z), fabsf(a.w - b.w));
                uint32 pp0 = bfp2(a.x * b.x, a.y * b.y);
                uint32 pp1 = bfp2(a.z * b.z, a.w * b.w);
                *(uint2*)(arow + 0 * 128 + i * 8) = make_uint2(hu0, hu1);
                *(uint2*)(arow + 1 * 128 + i * 8) = make_uint2(hv0, hv1);
                *(uint2*)(arow + 2 * 128 + i * 8) = make_uint2(dd0, dd1);
                *(uint2*)(arow + 3 * 128 + i * 8) = make_uint2(pp0, pp1);
            }
        }
        __syncwarp();

        // ---- mma: 16 k-steps, 8 n-tiles
        float acc[8][4];
        #pragma unroll
        for (int n = 0; n < 8; n++)
            #pragma unroll
            for (int j = 0; j < 4; j++) acc[n][j] = 0.f;

        #pragma unroll 4
        for (int kk = 0; kk < 16; kk++) {
            uint32 a[4];
            ldsm4(a, a_addr + kk * 32);
            #pragma unroll
            for (int p = 0; p < 4; p++) {
                uint32 b[4];
                ldsm4(b, b_base + (uint32)(p * 16) * ASTR + kk * 32);
                mma16816(acc[2 * p],     a, b[0], b[1]);
                mma16816(acc[2 * p + 1], a, b[2], b[3]);
            }
        }
        __syncwarp();

        // ---- epilogue: rows r0 = R+lane/4, r1 = r0+8
        float s0 = 0.f, s1 = 0.f;
        #pragma unroll
        for (int nt = 0; nt < 8; nt++) {
            #pragma unroll
            for (int j = 0; j < 2; j++) {
                float w = wbv[nt * 2 + j], bv = bav[nt * 2 + j];
                s0 += fmaxf(acc[nt][j] + bv, 0.f) * w;
                s1 += fmaxf(acc[nt][2 + j] + bv, 0.f) * w;
            }
        }
        s0 += __shfl_xor_sync(0xffffffffu, s0, 1);
        s0 += __shfl_xor_sync(0xffffffffu, s0, 2);
        s1 += __shfl_xor_sync(0xffffffffu, s1, 1);
        s1 += __shfl_xor_sync(0xffffffffu, s1, 2);
        if ((lane & 3) == 0) {
            int e0 = t * 64 + R + (lane >> 2);
            float logit0 = (s0 + bb0) * inv_tau;
            float x0 = (e0 < EP) ? logit0 : -logit0;
            float ls0 = fminf(x0, 0.f) - log1pf(expf(-fabsf(x0)));
            lsum += (e0 < EP) ? 5.0 * (double)ls0 : (double)ls0;
            int e1 = e0 + 8;
            float logit1 = (s1 + bb0) * inv_tau;
            float x1 = (e1 < EP) ? logit1 : -logit1;
            float ls1 = fminf(x1, 0.f) - log1pf(expf(-fabsf(x1)));
            lsum += (e1 < EP) ? 5.0 * (double)ls1 : (double)ls1;
        }
        __syncwarp();
    }

    #pragma unroll
    for (int o = 16; o; o >>= 1) lsum += __shfl_xor_sync(0xffffffffu, lsum, o);
    if (lane == 0) atomicAdd(&g_acc[0], lsum);
}

// ---------------- finalize ----------------
__global__ void fin_k(float* out) {
    float recon = -(float)(g_acc[0] / (double)ET);
    float kl = -0.5f * (float)(g_acc[1] / (double)(Nn * ZD));
    out[0] = recon + kl;
    out[1] = recon;
    out[2] = kl;
}

// ---------------- launch ----------------
extern "C" void kernel_launch(void* const* d_in, const int* in_sizes, int n_in,
                              void* d_out, int out_size)
{
    const float* x    = (const float*)d_in[0];
    const float* eps  = (const float*)d_in[1];
    const int* eidx   = (const int*)d_in[2];
    const int* pedge  = (const int*)d_in[3];
    const int* nedge  = (const int*)d_in[4];
    const float* W1   = (const float*)d_in[5];
    const float* b1   = (const float*)d_in[6];
    const float* g1   = (const float*)d_in[7];
    const float* bt1  = (const float*)d_in[8];
    const float* Wmu  = (const float*)d_in[9];
    const float* bmu  = (const float*)d_in[10];
    const float* Wlv  = (const float*)d_in[11];
    const float* blv  = (const float*)d_in[12];
    const float* Wd1  = (const float*)d_in[13];
    const float* bd1  = (const float*)d_in[14];
    const float* Wd2  = (const float*)d_in[15];
    const float* bd2  = (const float*)d_in[16];
    const float* Wa   = (const float*)d_in[17];
    const float* ba   = (const float*)d_in[18];
    const float* Wb   = (const float*)d_in[19];
    const float* bb   = (const float*)d_in[20];
    const float* tau  = (const float*)d_in[21];

    const int* src = eidx;
    const int* dst = eidx + E2;
    const int* ps  = pedge;
    const int* pd  = pedge + EP;
    const int* nu  = nedge;
    const int* nv  = nedge + EN;

    float *p_m1, *p_mlv, *p_mulv, *p_z, *p_dm, *p_hA, *p_hB, *p_agg1;
    cudaGetSymbolAddress((void**)&p_m1, g_m1);
    cudaGetSymbolAddress((void**)&p_agg1, g_agg1);
    cudaGetSymbolAddress((void**)&p_mlv, g_mlv);
    cudaGetSymbolAddress((void**)&p_mulv, g_mulv);
    cudaGetSymbolAddress((void**)&p_z, g_z);
    cudaGetSymbolAddress((void**)&p_dm, g_dm);
    cudaGetSymbolAddress((void**)&p_hA, g_hA);
    cudaGetSymbolAddress((void**)&p_hB, g_hB);

    cudaFuncSetAttribute(edge_hmma_k, cudaFuncAttributeMaxDynamicSharedMemorySize, E_SMEM);

    zero_k<<<2048, 256>>>();

    // encoder: m1 = x @ W1
    gemm_k<<<dim3(4, 313), 256>>>(x, W1, p_m1, Nn, 256, 256, 256, 256, 256);
    scatter_add_k<<<(E2 * 64 + 255) / 256, 256>>>(p_m1, p_agg1, src, dst, E2, 64);
    ln_relu_k<<<2500, 256>>>(b1, g1, bt1);

    // mu/lv pre-scatter GEMMs into [mu|lv] buffer
    gemm_k<<<dim3(1, 313), 256>>>(p_m1, Wmu, p_mlv,      Nn, 64, 256, 256, 64, 128);
    gemm_k<<<dim3(1, 313), 256>>>(p_m1, Wlv, p_mlv + 64, Nn, 64, 256, 256, 64, 128);
    scatter_add_k<<<(E2 * 32 + 255) / 256, 256>>>(p_mlv, p_mulv, src, dst, E2, 32);

    z_kl_k<<<5000, 256>>>(eps, bmu, blv);

    deg_k<<<(EP + 255) / 256, 256>>>(pd);
    dis_k<<<(Nn + 255) / 256, 256>>>();

    // decoder pass 1
    gemm_k<<<dim3(1, 313), 256>>>(p_z, Wd1, p_dm, Nn, 64, 64, 64, 64, 64);
    scat_norm_k<<<(EP * 16 + 255) / 256, 256>>>(p_dm, p_hA, ps, pd);
    relu_dec_k<<<(Nn * 64 + 255) / 256, 256>>>(p_dm, p_hA, bd1);

    // decoder pass 2
    gemm_k<<<dim3(1, 313), 256>>>(p_hA, Wd2, p_dm, Nn, 64, 64, 64, 64, 64);
    scat_norm_k<<<(EP * 16 + 255) / 256, 256>>>(p_dm, p_hB, ps, pd);
    relu_dec_k<<<(Nn * 64 + 255) / 256, 256>>>(p_dm, p_hB, bd2);

    // fused edge MLP + weighted BCE on HMMA tensor path
    edge_hmma_k<<<592, 128, E_SMEM>>>(Wa, ba, Wb, bb, ps, pd, nu, nv, tau);

    fin_k<<<1, 1>>>((float*)d_out);
}